// round 1
// baseline (speedup 1.0000x reference)
#include <cuda_runtime.h>

#define SEQ 2048
#define HIDDEN 2048
#define NH 16
#define NKV 2
#define HD 128
#define KVW (NKV*HD)          // 256
#define ATT_SCALE 0.08838834764831845f

// Scratch (no allocations allowed)
__device__ float g_Q[SEQ*HIDDEN];    // (s, h*128+d)
__device__ float g_K[SEQ*KVW];       // (s, kvh*128+d)
__device__ float g_V[SEQ*KVW];
__device__ float g_C[SEQ*HIDDEN];    // attention context (s, h*128+d)

// ---------------------------------------------------------------------------
// Generic 128x128 block fp32 GEMM: C[m0:+128, n0:+128] = A @ W (+ bias)
// A: [M, lda] row-major, W: [K, ldw] row-major. 256 threads, 8x8 microtile.
// ---------------------------------------------------------------------------
__device__ __forceinline__ void gemm_block(
    const float* __restrict__ A, int lda,
    const float* __restrict__ W, int ldw,
    const float* __restrict__ bias,
    float* __restrict__ C, int ldc,
    int m0, int n0, int Kdim)
{
    __shared__ float As[8][128];
    __shared__ float Bs[8][128];
    const int t  = threadIdx.x;
    const int tx = t & 15;
    const int ty = t >> 4;

    float acc[8][8];
    #pragma unroll
    for (int i = 0; i < 8; i++)
        #pragma unroll
        for (int j = 0; j < 8; j++) acc[i][j] = 0.f;

    const int arow = t >> 1;          // 0..127
    const int acol = (t & 1) * 4;     // 0 or 4
    const int brow = t >> 5;          // 0..7
    const int bcol = (t & 31) * 4;    // 0..124

    const float* Ap = A + (size_t)(m0 + arow) * lda + acol;
    const float* Wp = W + (size_t)brow * ldw + n0 + bcol;

    for (int k0 = 0; k0 < Kdim; k0 += 8) {
        float4 a4 = *(const float4*)(Ap + k0);
        float4 b4 = *(const float4*)(Wp + (size_t)k0 * ldw);
        __syncthreads();
        As[acol + 0][arow] = a4.x;
        As[acol + 1][arow] = a4.y;
        As[acol + 2][arow] = a4.z;
        As[acol + 3][arow] = a4.w;
        *(float4*)&Bs[brow][bcol] = b4;
        __syncthreads();
        #pragma unroll
        for (int kk = 0; kk < 8; kk++) {
            float ar[8], br[8];
            #pragma unroll
            for (int i = 0; i < 8; i++) ar[i] = As[kk][ty * 8 + i];
            #pragma unroll
            for (int j = 0; j < 8; j++) br[j] = Bs[kk][tx * 8 + j];
            #pragma unroll
            for (int i = 0; i < 8; i++)
                #pragma unroll
                for (int j = 0; j < 8; j++) acc[i][j] += ar[i] * br[j];
        }
    }

    #pragma unroll
    for (int i = 0; i < 8; i++) {
        const int row = m0 + ty * 8 + i;
        #pragma unroll
        for (int j = 0; j < 8; j += 4) {
            const int col = n0 + tx * 8 + j;
            float4 v;
            v.x = acc[i][j + 0];
            v.y = acc[i][j + 1];
            v.z = acc[i][j + 2];
            v.w = acc[i][j + 3];
            if (bias) {
                v.x += bias[col + 0];
                v.y += bias[col + 1];
                v.z += bias[col + 2];
                v.w += bias[col + 3];
            }
            *(float4*)(C + (size_t)row * ldc + col) = v;
        }
    }
}

// ---------------------------------------------------------------------------
// Fused QKV projection: grid (20, 16). n-blocks 0..15 -> Q, 16..17 -> K, 18..19 -> V
// ---------------------------------------------------------------------------
__global__ void __launch_bounds__(256) qkv_kernel(
    const float* __restrict__ hs,
    const float* __restrict__ Wq, const float* __restrict__ bq,
    const float* __restrict__ Wk, const float* __restrict__ bk,
    const float* __restrict__ Wv, const float* __restrict__ bv)
{
    const int bn = blockIdx.x;
    const int m0 = blockIdx.y * 128;
    if (bn < 16) {
        gemm_block(hs, HIDDEN, Wq, HIDDEN, bq, g_Q, HIDDEN, m0, bn * 128, HIDDEN);
    } else if (bn < 18) {
        gemm_block(hs, HIDDEN, Wk, KVW, bk, g_K, KVW, m0, (bn - 16) * 128, HIDDEN);
    } else {
        gemm_block(hs, HIDDEN, Wv, KVW, bv, g_V, KVW, m0, (bn - 18) * 128, HIDDEN);
    }
}

// ---------------------------------------------------------------------------
// O projection: grid (16, 16)
// ---------------------------------------------------------------------------
__global__ void __launch_bounds__(256) oproj_kernel(
    const float* __restrict__ Wo, float* __restrict__ out)
{
    gemm_block(g_C, HIDDEN, Wo, HIDDEN, nullptr, out, HIDDEN,
               blockIdx.y * 128, blockIdx.x * 128, HIDDEN);
}

// ---------------------------------------------------------------------------
// RoPE in place. X layout [SEQ, nheads*128]. Each thread handles one (s,h,d<64) pair.
// which=1 -> g_Q (nheads=16), which=0 -> g_K (nheads=2)
// ---------------------------------------------------------------------------
__global__ void rope_kernel(const float* __restrict__ cosT,
                            const float* __restrict__ sinT,
                            int nheads, int which)
{
    float* X = which ? g_Q : g_K;
    const int idx = blockIdx.x * blockDim.x + threadIdx.x;
    const int total = SEQ * nheads * 64;
    if (idx >= total) return;
    const int d = idx & 63;
    const int h = (idx >> 6) % nheads;
    const int s = idx / (64 * nheads);

    const float c1 = cosT[s * HD + d];
    const float s1 = sinT[s * HD + d];
    const float c2 = cosT[s * HD + d + 64];
    const float s2 = sinT[s * HD + d + 64];

    float* p = X + (size_t)s * (nheads * HD) + h * HD + d;
    const float x1 = p[0];
    const float x2 = p[64];
    p[0]  = x1 * c1 - x2 * s1;
    p[64] = x2 * c2 + x1 * s2;
}

// ---------------------------------------------------------------------------
// Flash attention, causal, GQA (8 query heads per kv head).
// Grid: (32 q-tiles of 64, 16 heads). Block: 256 threads = 64 rows x 4 lanes.
// Lane c of a row owns dims d = c*4 + 16*i (i=0..7), keeping q and O in regs.
// One 32KB smem buffer reused: stage K tile (score phase) then V tile (accum).
// ---------------------------------------------------------------------------
__global__ void __launch_bounds__(256, 1) attn_kernel()
{
    __shared__ float sKV[64 * 128];
    const int t = threadIdx.x;
    const int c = t & 3;
    const int r = t >> 2;                 // 0..63
    const int qt = blockIdx.x;            // 0..31
    const int h  = blockIdx.y;            // 0..15
    const int kvh = h >> 3;
    const int qrow = qt * 64 + r;

    const float* qp = g_Q + (size_t)qrow * HIDDEN + h * HD;
    float4 q[8], o[8];
    #pragma unroll
    for (int i = 0; i < 8; i++) {
        q[i] = *(const float4*)(qp + c * 4 + i * 16);
        o[i] = make_float4(0.f, 0.f, 0.f, 0.f);
    }
    float m = -1e30f, l = 0.f;

    for (int kt = 0; kt <= qt; kt++) {
        // ---- stage K tile ----
        __syncthreads();
        #pragma unroll
        for (int it = 0; it < 8; it++) {
            const int li = it * 1024 + t * 4;
            const int row = li >> 7, d = li & 127;
            *(float4*)&sKV[li] =
                *(const float4*)&g_K[(size_t)(kt * 64 + row) * KVW + kvh * HD + d];
        }
        __syncthreads();

        float sc[64];
        #pragma unroll
        for (int j = 0; j < 64; j++) {
            float p = 0.f;
            #pragma unroll
            for (int i = 0; i < 8; i++) {
                const float4 k4 = *(const float4*)&sKV[j * 128 + c * 4 + i * 16];
                p += q[i].x * k4.x + q[i].y * k4.y + q[i].z * k4.z + q[i].w * k4.w;
            }
            p += __shfl_xor_sync(0xffffffffu, p, 1);
            p += __shfl_xor_sync(0xffffffffu, p, 2);
            sc[j] = p * ATT_SCALE;
        }

        if (kt == qt) {
            #pragma unroll
            for (int j = 0; j < 64; j++)
                if (j > r) sc[j] = -1e30f;
        }

        float mt = m;
        #pragma unroll
        for (int j = 0; j < 64; j++) mt = fmaxf(mt, sc[j]);
        const float corr = __expf(m - mt);
        m = mt;
        l *= corr;
        #pragma unroll
        for (int i = 0; i < 8; i++) {
            o[i].x *= corr; o[i].y *= corr; o[i].z *= corr; o[i].w *= corr;
        }

        // ---- stage V tile (reuse smem) ----
        __syncthreads();
        #pragma unroll
        for (int it = 0; it < 8; it++) {
            const int li = it * 1024 + t * 4;
            const int row = li >> 7, d = li & 127;
            *(float4*)&sKV[li] =
                *(const float4*)&g_V[(size_t)(kt * 64 + row) * KVW + kvh * HD + d];
        }
        __syncthreads();

        #pragma unroll
        for (int j = 0; j < 64; j++) {
            const float p = __expf(sc[j] - m);
            l += p;
            #pragma unroll
            for (int i = 0; i < 8; i++) {
                const float4 v4 = *(const float4*)&sKV[j * 128 + c * 4 + i * 16];
                o[i].x += p * v4.x; o[i].y += p * v4.y;
                o[i].z += p * v4.z; o[i].w += p * v4.w;
            }
        }
    }

    const float inv = 1.f / l;
    float* cp = g_C + (size_t)qrow * HIDDEN + h * HD;
    #pragma unroll
    for (int i = 0; i < 8; i++) {
        float4 v = o[i];
        v.x *= inv; v.y *= inv; v.z *= inv; v.w *= inv;
        *(float4*)(cp + c * 4 + i * 16) = v;
    }
}

// ---------------------------------------------------------------------------
extern "C" void kernel_launch(void* const* d_in, const int* in_sizes, int n_in,
                              void* d_out, int out_size)
{
    const float* hs   = (const float*)d_in[0];
    const float* cosT = (const float*)d_in[1];
    const float* sinT = (const float*)d_in[2];
    // d_in[3] = attention_mask (pure causal; applied analytically in attn_kernel)
    const float* Wq = (const float*)d_in[4];
    const float* bq = (const float*)d_in[5];
    const float* Wk = (const float*)d_in[6];
    const float* bk = (const float*)d_in[7];
    const float* Wv = (const float*)d_in[8];
    const float* bv = (const float*)d_in[9];
    const float* Wo = (const float*)d_in[10];
    float* out = (float*)d_out;

    qkv_kernel<<<dim3(20, 16), 256>>>(hs, Wq, bq, Wk, bk, Wv, bv);
    rope_kernel<<<(SEQ * NH * 64 + 255) / 256, 256>>>(cosT, sinT, NH, 1);
    rope_kernel<<<(SEQ * NKV * 64 + 255) / 256, 256>>>(cosT, sinT, NKV, 0);
    attn_kernel<<<dim3(32, 16), 256>>>();
    oproj_kernel<<<dim3(16, 16), 256>>>(Wo, out);
}

// round 3
// speedup vs baseline: 1.3737x; 1.3737x over previous
#include <cuda_runtime.h>

typedef unsigned int u32;

#define SEQ 2048
#define HIDDEN 2048
#define NH 16
#define NKV 2
#define HD 128
#define KVW (NKV*HD)          // 256
#define ATT_SCALE 0.08838834764831845f

// ---------------- scratch (no allocations allowed) ----------------
__device__ float g_Q[SEQ*HIDDEN];
__device__ float g_K[SEQ*KVW];
__device__ float g_V[SEQ*KVW];
__device__ float g_C[SEQ*HIDDEN];

// ---------------- helpers ----------------
__device__ __forceinline__ u32 f2tf32(float f) {
    u32 r;
    asm("cvt.rna.tf32.f32 %0, %1;" : "=r"(r) : "f"(f));
    return r;
}
__device__ __forceinline__ void mma_tf32(float* c, const u32* a, const u32* b) {
    asm volatile(
        "mma.sync.aligned.m16n8k8.row.col.f32.tf32.tf32.f32 "
        "{%0,%1,%2,%3}, {%4,%5,%6,%7}, {%8,%9}, {%0,%1,%2,%3};"
        : "+f"(c[0]), "+f"(c[1]), "+f"(c[2]), "+f"(c[3])
        : "r"(a[0]), "r"(a[1]), "r"(a[2]), "r"(a[3]),
          "r"(b[0]), "r"(b[1]));
}

// ---------------------------------------------------------------------------
// tf32 mma.sync GEMM: C[M,N] = A[M,K] @ W[K,N] (+bias)
// Block 256 thr = 8 warps (2 M x 4 N), block tile 128x128, K-chunk 32.
// ---------------------------------------------------------------------------
#define SA_LD 36
#define SB_LD 132

__global__ void __launch_bounds__(256) mma_gemm_kernel(
    const float* __restrict__ A_ext,
    const float* __restrict__ W,
    const float* __restrict__ bias,
    float* __restrict__ C_ext,
    int Kdim, int Nw, int asel, int csel)
{
    __shared__ u32 sA[128 * SA_LD];
    __shared__ u32 sB[32 * SB_LD];

    const float* A = asel ? g_C : A_ext;
    float* C = (csel == 0) ? C_ext : (csel == 1) ? g_Q : (csel == 2) ? g_K : g_V;

    const int t = threadIdx.x;
    const int wid = t >> 5, lane = t & 31;
    const int warpM = wid & 1, warpN = wid >> 1;
    const int g = lane >> 2, tg = lane & 3;
    const int row0 = blockIdx.y * 128, col0 = blockIdx.x * 128;

    float c[4][4][4];
    #pragma unroll
    for (int i = 0; i < 4; i++)
        #pragma unroll
        for (int j = 0; j < 4; j++)
            #pragma unroll
            for (int r = 0; r < 4; r++) c[i][j][r] = 0.f;

    // global load coords
    const int arow = t >> 3;           // 0..31 (4 passes of 32 rows)
    const int ak4  = (t & 7) * 4;      // k offset 0..28
    const int bkrow = t >> 5;          // 0..7 (4 passes of 8 k-rows)
    const int bcol4 = (t & 31) * 4;    // 0..124

    const float* Ap = A + (size_t)(row0 + arow) * Kdim + ak4;
    const float* Bp = W + (size_t)bkrow * Nw + col0 + bcol4;
    const size_t aRow32 = (size_t)32 * Kdim;
    const size_t bRow8  = (size_t)8 * Nw;

    const int NCH = Kdim >> 5;

    float4 ar[4], br[4];
    #pragma unroll
    for (int p = 0; p < 4; p++) {
        ar[p] = *(const float4*)(Ap + p * aRow32);
        br[p] = *(const float4*)(Bp + p * bRow8);
    }

    const u32* sAw = sA + (warpM * 64) * SA_LD;
    const int bcolw = warpN * 32;

    for (int ch = 0; ch < NCH; ch++) {
        __syncthreads();
        #pragma unroll
        for (int p = 0; p < 4; p++) {
            u32* da = &sA[(arow + p * 32) * SA_LD + ak4];
            da[0] = f2tf32(ar[p].x); da[1] = f2tf32(ar[p].y);
            da[2] = f2tf32(ar[p].z); da[3] = f2tf32(ar[p].w);
            u32* db = &sB[(bkrow + p * 8) * SB_LD + bcol4];
            db[0] = f2tf32(br[p].x); db[1] = f2tf32(br[p].y);
            db[2] = f2tf32(br[p].z); db[3] = f2tf32(br[p].w);
        }
        __syncthreads();

        if (ch + 1 < NCH) {
            const int ko = (ch + 1) * 32;
            #pragma unroll
            for (int p = 0; p < 4; p++) {
                ar[p] = *(const float4*)(Ap + ko + p * aRow32);
                br[p] = *(const float4*)(Bp + (size_t)ko * Nw + p * bRow8);
            }
        }

        #pragma unroll
        for (int ks = 0; ks < 4; ks++) {
            const int kb = ks * 8;
            u32 af[4][4], bf[4][2];
            #pragma unroll
            for (int i = 0; i < 4; i++) {
                const u32* base = sAw + (i * 16 + g) * SA_LD + kb + tg;
                af[i][0] = base[0];
                af[i][1] = base[8 * SA_LD];
                af[i][2] = base[4];
                af[i][3] = base[8 * SA_LD + 4];
            }
            #pragma unroll
            for (int j = 0; j < 4; j++) {
                const u32* base = sB + (kb + tg) * SB_LD + bcolw + j * 8 + g;
                bf[j][0] = base[0];
                bf[j][1] = base[4 * SB_LD];
            }
            #pragma unroll
            for (int i = 0; i < 4; i++)
                #pragma unroll
                for (int j = 0; j < 4; j++)
                    mma_tf32(c[i][j], af[i], bf[j]);
        }
    }

    // epilogue
    #pragma unroll
    for (int i = 0; i < 4; i++) {
        const int r0 = row0 + warpM * 64 + i * 16 + g;
        #pragma unroll
        for (int j = 0; j < 4; j++) {
            const int col = col0 + warpN * 32 + j * 8 + 2 * tg;
            float b0 = 0.f, b1 = 0.f;
            if (bias) { b0 = bias[col]; b1 = bias[col + 1]; }
            float2 v0 = make_float2(c[i][j][0] + b0, c[i][j][1] + b1);
            float2 v1 = make_float2(c[i][j][2] + b0, c[i][j][3] + b1);
            *(float2*)(C + (size_t)r0 * Nw + col) = v0;
            *(float2*)(C + (size_t)(r0 + 8) * Nw + col) = v1;
        }
    }
}

// ---------------------------------------------------------------------------
// RoPE in place
// ---------------------------------------------------------------------------
__global__ void rope_kernel(const float* __restrict__ cosT,
                            const float* __restrict__ sinT,
                            int nheads, int which)
{
    float* X = which ? g_Q : g_K;
    const int idx = blockIdx.x * blockDim.x + threadIdx.x;
    const int total = SEQ * nheads * 64;
    if (idx >= total) return;
    const int d = idx & 63;
    const int h = (idx >> 6) % nheads;
    const int s = idx / (64 * nheads);

    const float c1 = cosT[s * HD + d];
    const float s1 = sinT[s * HD + d];
    const float c2 = cosT[s * HD + d + 64];
    const float s2 = sinT[s * HD + d + 64];

    float* p = X + (size_t)s * (nheads * HD) + h * HD + d;
    const float x1 = p[0];
    const float x2 = p[64];
    p[0]  = x1 * c1 - x2 * s1;
    p[64] = x2 * c2 + x1 * s2;
}

// ---------------------------------------------------------------------------
// Flash attention (SIMT, unchanged), causal, GQA.
// ---------------------------------------------------------------------------
__global__ void __launch_bounds__(256, 1) attn_kernel()
{
    __shared__ float sKV[64 * 128];
    const int t = threadIdx.x;
    const int c = t & 3;
    const int r = t >> 2;
    const int qt = blockIdx.x;
    const int h  = blockIdx.y;
    const int kvh = h >> 3;
    const int qrow = qt * 64 + r;

    const float* qp = g_Q + (size_t)qrow * HIDDEN + h * HD;
    float4 q[8], o[8];
    #pragma unroll
    for (int i = 0; i < 8; i++) {
        q[i] = *(const float4*)(qp + c * 4 + i * 16);
        o[i] = make_float4(0.f, 0.f, 0.f, 0.f);
    }
    float m = -1e30f, l = 0.f;

    for (int kt = 0; kt <= qt; kt++) {
        __syncthreads();
        #pragma unroll
        for (int it = 0; it < 8; it++) {
            const int li = it * 1024 + t * 4;
            const int row = li >> 7, d = li & 127;
            *(float4*)&sKV[li] =
                *(const float4*)&g_K[(size_t)(kt * 64 + row) * KVW + kvh * HD + d];
        }
        __syncthreads();

        float sc[64];
        #pragma unroll
        for (int j = 0; j < 64; j++) {
            float p = 0.f;
            #pragma unroll
            for (int i = 0; i < 8; i++) {
                const float4 k4 = *(const float4*)&sKV[j * 128 + c * 4 + i * 16];
                p += q[i].x * k4.x + q[i].y * k4.y + q[i].z * k4.z + q[i].w * k4.w;
            }
            p += __shfl_xor_sync(0xffffffffu, p, 1);
            p += __shfl_xor_sync(0xffffffffu, p, 2);
            sc[j] = p * ATT_SCALE;
        }

        if (kt == qt) {
            #pragma unroll
            for (int j = 0; j < 64; j++)
                if (j > r) sc[j] = -1e30f;
        }

        float mt = m;
        #pragma unroll
        for (int j = 0; j < 64; j++) mt = fmaxf(mt, sc[j]);
        const float corr = __expf(m - mt);
        m = mt;
        l *= corr;
        #pragma unroll
        for (int i = 0; i < 8; i++) {
            o[i].x *= corr; o[i].y *= corr; o[i].z *= corr; o[i].w *= corr;
        }

        __syncthreads();
        #pragma unroll
        for (int it = 0; it < 8; it++) {
            const int li = it * 1024 + t * 4;
            const int row = li >> 7, d = li & 127;
            *(float4*)&sKV[li] =
                *(const float4*)&g_V[(size_t)(kt * 64 + row) * KVW + kvh * HD + d];
        }
        __syncthreads();

        #pragma unroll
        for (int j = 0; j < 64; j++) {
            const float p = __expf(sc[j] - m);
            l += p;
            #pragma unroll
            for (int i = 0; i < 8; i++) {
                const float4 v4 = *(const float4*)&sKV[j * 128 + c * 4 + i * 16];
                o[i].x += p * v4.x; o[i].y += p * v4.y;
                o[i].z += p * v4.z; o[i].w += p * v4.w;
            }
        }
    }

    const float inv = 1.f / l;
    float* cp = g_C + (size_t)qrow * HIDDEN + h * HD;
    #pragma unroll
    for (int i = 0; i < 8; i++) {
        float4 v = o[i];
        v.x *= inv; v.y *= inv; v.z *= inv; v.w *= inv;
        *(float4*)(cp + c * 4 + i * 16) = v;
    }
}

// ---------------------------------------------------------------------------
extern "C" void kernel_launch(void* const* d_in, const int* in_sizes, int n_in,
                              void* d_out, int out_size)
{
    const float* hs   = (const float*)d_in[0];
    const float* cosT = (const float*)d_in[1];
    const float* sinT = (const float*)d_in[2];
    // d_in[3] = attention_mask (pure causal; applied analytically)
    const float* Wq = (const float*)d_in[4];
    const float* bq = (const float*)d_in[5];
    const float* Wk = (const float*)d_in[6];
    const float* bk = (const float*)d_in[7];
    const float* Wv = (const float*)d_in[8];
    const float* bv = (const float*)d_in[9];
    const float* Wo = (const float*)d_in[10];
    float* out = (float*)d_out;

    mma_gemm_kernel<<<dim3(16, 16), 256>>>(hs, Wq, bq, nullptr, HIDDEN, HIDDEN, 0, 1);
    mma_gemm_kernel<<<dim3(2,  16), 256>>>(hs, Wk, bk, nullptr, HIDDEN, KVW,    0, 2);
    mma_gemm_kernel<<<dim3(2,  16), 256>>>(hs, Wv, bv, nullptr, HIDDEN, KVW,    0, 3);

    rope_kernel<<<(SEQ * NH  * 64 + 255) / 256, 256>>>(cosT, sinT, NH, 1);
    rope_kernel<<<(SEQ * NKV * 64 + 255) / 256, 256>>>(cosT, sinT, NKV, 0);

    attn_kernel<<<dim3(32, 16), 256>>>();

    mma_gemm_kernel<<<dim3(16, 16), 256>>>(nullptr, Wo, nullptr, out, HIDDEN, HIDDEN, 1, 0);
}

// round 4
// speedup vs baseline: 3.5916x; 2.6145x over previous
#include <cuda_runtime.h>

typedef unsigned int u32;

#define SEQ 2048
#define HIDDEN 2048
#define NH 16
#define NKV 2
#define HD 128
#define KVW (NKV*HD)          // 256
#define ATT_SCALE 0.08838834764831845f

// ---------------- scratch (no allocations allowed) ----------------
__device__ float g_Q[SEQ*HIDDEN];
__device__ float g_K[SEQ*KVW];
__device__ float g_V[SEQ*KVW];
__device__ float g_C[SEQ*HIDDEN];

// ---------------- helpers ----------------
__device__ __forceinline__ u32 f2tf32(float f) {
    u32 r;
    asm("cvt.rna.tf32.f32 %0, %1;" : "=r"(r) : "f"(f));
    return r;
}
__device__ __forceinline__ void mma_tf32(float* c, const u32* a, const u32* b) {
    asm volatile(
        "mma.sync.aligned.m16n8k8.row.col.f32.tf32.tf32.f32 "
        "{%0,%1,%2,%3}, {%4,%5,%6,%7}, {%8,%9}, {%0,%1,%2,%3};"
        : "+f"(c[0]), "+f"(c[1]), "+f"(c[2]), "+f"(c[3])
        : "r"(a[0]), "r"(a[1]), "r"(a[2]), "r"(a[3]),
          "r"(b[0]), "r"(b[1]));
}

// ---------------------------------------------------------------------------
// tf32 mma.sync GEMM: C[M,N] = A[M,K] @ W[K,N] (+bias)   (unchanged)
// ---------------------------------------------------------------------------
#define SA_LD 36
#define SB_LD 132

__global__ void __launch_bounds__(256) mma_gemm_kernel(
    const float* __restrict__ A_ext,
    const float* __restrict__ W,
    const float* __restrict__ bias,
    float* __restrict__ C_ext,
    int Kdim, int Nw, int asel, int csel)
{
    __shared__ u32 sA[128 * SA_LD];
    __shared__ u32 sB[32 * SB_LD];

    const float* A = asel ? g_C : A_ext;
    float* C = (csel == 0) ? C_ext : (csel == 1) ? g_Q : (csel == 2) ? g_K : g_V;

    const int t = threadIdx.x;
    const int wid = t >> 5, lane = t & 31;
    const int warpM = wid & 1, warpN = wid >> 1;
    const int g = lane >> 2, tg = lane & 3;
    const int row0 = blockIdx.y * 128, col0 = blockIdx.x * 128;

    float c[4][4][4];
    #pragma unroll
    for (int i = 0; i < 4; i++)
        #pragma unroll
        for (int j = 0; j < 4; j++)
            #pragma unroll
            for (int r = 0; r < 4; r++) c[i][j][r] = 0.f;

    const int arow = t >> 3;
    const int ak4  = (t & 7) * 4;
    const int bkrow = t >> 5;
    const int bcol4 = (t & 31) * 4;

    const float* Ap = A + (size_t)(row0 + arow) * Kdim + ak4;
    const float* Bp = W + (size_t)bkrow * Nw + col0 + bcol4;
    const size_t aRow32 = (size_t)32 * Kdim;
    const size_t bRow8  = (size_t)8 * Nw;

    const int NCH = Kdim >> 5;

    float4 ar[4], br[4];
    #pragma unroll
    for (int p = 0; p < 4; p++) {
        ar[p] = *(const float4*)(Ap + p * aRow32);
        br[p] = *(const float4*)(Bp + p * bRow8);
    }

    const u32* sAw = sA + (warpM * 64) * SA_LD;
    const int bcolw = warpN * 32;

    for (int ch = 0; ch < NCH; ch++) {
        __syncthreads();
        #pragma unroll
        for (int p = 0; p < 4; p++) {
            u32* da = &sA[(arow + p * 32) * SA_LD + ak4];
            da[0] = f2tf32(ar[p].x); da[1] = f2tf32(ar[p].y);
            da[2] = f2tf32(ar[p].z); da[3] = f2tf32(ar[p].w);
            u32* db = &sB[(bkrow + p * 8) * SB_LD + bcol4];
            db[0] = f2tf32(br[p].x); db[1] = f2tf32(br[p].y);
            db[2] = f2tf32(br[p].z); db[3] = f2tf32(br[p].w);
        }
        __syncthreads();

        if (ch + 1 < NCH) {
            const int ko = (ch + 1) * 32;
            #pragma unroll
            for (int p = 0; p < 4; p++) {
                ar[p] = *(const float4*)(Ap + ko + p * aRow32);
                br[p] = *(const float4*)(Bp + (size_t)ko * Nw + p * bRow8);
            }
        }

        #pragma unroll
        for (int ks = 0; ks < 4; ks++) {
            const int kb = ks * 8;
            u32 af[4][4], bf[4][2];
            #pragma unroll
            for (int i = 0; i < 4; i++) {
                const u32* base = sAw + (i * 16 + g) * SA_LD + kb + tg;
                af[i][0] = base[0];
                af[i][1] = base[8 * SA_LD];
                af[i][2] = base[4];
                af[i][3] = base[8 * SA_LD + 4];
            }
            #pragma unroll
            for (int j = 0; j < 4; j++) {
                const u32* base = sB + (kb + tg) * SB_LD + bcolw + j * 8 + g;
                bf[j][0] = base[0];
                bf[j][1] = base[4 * SB_LD];
            }
            #pragma unroll
            for (int i = 0; i < 4; i++)
                #pragma unroll
                for (int j = 0; j < 4; j++)
                    mma_tf32(c[i][j], af[i], bf[j]);
        }
    }

    #pragma unroll
    for (int i = 0; i < 4; i++) {
        const int r0 = row0 + warpM * 64 + i * 16 + g;
        #pragma unroll
        for (int j = 0; j < 4; j++) {
            const int col = col0 + warpN * 32 + j * 8 + 2 * tg;
            float b0 = 0.f, b1 = 0.f;
            if (bias) { b0 = bias[col]; b1 = bias[col + 1]; }
            float2 v0 = make_float2(c[i][j][0] + b0, c[i][j][1] + b1);
            float2 v1 = make_float2(c[i][j][2] + b0, c[i][j][3] + b1);
            *(float2*)(C + (size_t)r0 * Nw + col) = v0;
            *(float2*)(C + (size_t)(r0 + 8) * Nw + col) = v1;
        }
    }
}

// ---------------------------------------------------------------------------
// RoPE in place (unchanged)
// ---------------------------------------------------------------------------
__global__ void rope_kernel(const float* __restrict__ cosT,
                            const float* __restrict__ sinT,
                            int nheads, int which)
{
    float* X = which ? g_Q : g_K;
    const int idx = blockIdx.x * blockDim.x + threadIdx.x;
    const int total = SEQ * nheads * 64;
    if (idx >= total) return;
    const int d = idx & 63;
    const int h = (idx >> 6) % nheads;
    const int s = idx / (64 * nheads);

    const float c1 = cosT[s * HD + d];
    const float s1 = sinT[s * HD + d];
    const float c2 = cosT[s * HD + d + 64];
    const float s2 = sinT[s * HD + d + 64];

    float* p = X + (size_t)s * (nheads * HD) + h * HD + d;
    const float x1 = p[0];
    const float x2 = p[64];
    p[0]  = x1 * c1 - x2 * s1;
    p[64] = x2 * c2 + x1 * s2;
}

// ---------------------------------------------------------------------------
// mma.sync tf32 flash attention. Block: 1 head x 128 q-rows, 8 warps x 16 rows.
// K-tile 64. K smem [64][132], V smem [64][136] (both row-major, no transpose).
// ---------------------------------------------------------------------------
#define SK_LD 132
#define SV_LD 136
#define SK_WORDS (64 * SK_LD)
#define SV_WORDS (64 * SV_LD)
#define ATTN_SMEM ((SK_WORDS + SV_WORDS) * 4)

__global__ void __launch_bounds__(256, 1) attn_mma_kernel()
{
    extern __shared__ u32 smem[];
    u32* sK = smem;                 // [64][SK_LD]
    u32* sV = smem + SK_WORDS;      // [64][SV_LD]

    const int t = threadIdx.x;
    const int lane = t & 31, wid = t >> 5;
    const int g = lane >> 2, tg = lane & 3;
    const int qt = 15 - blockIdx.x;          // heavy tiles first
    const int h  = blockIdx.y;
    const int kvh = h >> 3;
    const int qbase = qt * 128 + wid * 16;
    const int r0 = qbase + g, r1 = qbase + g + 8;

    // Q fragments (tf32) in registers: rows r0/r1, all 128 dims
    u32 qf[16][4];
    const float* Qp = g_Q + (size_t)qbase * HIDDEN + h * HD;
    #pragma unroll
    for (int ks = 0; ks < 16; ks++) {
        qf[ks][0] = f2tf32(Qp[(size_t)g * HIDDEN + ks * 8 + tg]);
        qf[ks][1] = f2tf32(Qp[(size_t)(g + 8) * HIDDEN + ks * 8 + tg]);
        qf[ks][2] = f2tf32(Qp[(size_t)g * HIDDEN + ks * 8 + tg + 4]);
        qf[ks][3] = f2tf32(Qp[(size_t)(g + 8) * HIDDEN + ks * 8 + tg + 4]);
    }

    float o[16][4];
    #pragma unroll
    for (int n = 0; n < 16; n++)
        #pragma unroll
        for (int r = 0; r < 4; r++) o[n][r] = 0.f;
    float m0 = -1e30f, m1 = -1e30f, l0 = 0.f, l1 = 0.f;

    const int ntiles = 2 * qt + 2;

    for (int kt = 0; kt < ntiles; kt++) {
        __syncthreads();
        // stage K/V tile (64x128) as tf32
        #pragma unroll
        for (int p = 0; p < 8; p++) {
            const int idx = p * 256 + t;
            const int r = idx >> 5;
            const int c4 = (idx & 31) << 2;
            const size_t goff = (size_t)(kt * 64 + r) * KVW + kvh * HD + c4;
            float4 kk = *(const float4*)&g_K[goff];
            float4 vv = *(const float4*)&g_V[goff];
            u32* dk = sK + r * SK_LD + c4;
            dk[0] = f2tf32(kk.x); dk[1] = f2tf32(kk.y);
            dk[2] = f2tf32(kk.z); dk[3] = f2tf32(kk.w);
            u32* dv = sV + r * SV_LD + c4;
            dv[0] = f2tf32(vv.x); dv[1] = f2tf32(vv.y);
            dv[2] = f2tf32(vv.z); dv[3] = f2tf32(vv.w);
        }
        __syncthreads();

        if (kt * 64 > qbase + 15) continue;   // fully masked for this warp

        // ---- S = Q K^T (16 x 64) ----
        float c[8][4];
        #pragma unroll
        for (int j = 0; j < 8; j++)
            #pragma unroll
            for (int r = 0; r < 4; r++) c[j][r] = 0.f;

        #pragma unroll
        for (int ks = 0; ks < 16; ks++) {
            #pragma unroll
            for (int j = 0; j < 8; j++) {
                u32 bf[2];
                const u32* bb = sK + (j * 8 + g) * SK_LD + ks * 8 + tg;
                bf[0] = bb[0];
                bf[1] = bb[4];
                mma_tf32(c[j], qf[ks], bf);
            }
        }

        // ---- scale + causal mask ----
        const bool diag = (kt * 64 + 63 > qbase);
        #pragma unroll
        for (int j = 0; j < 8; j++) {
            const int key = kt * 64 + j * 8 + 2 * tg;
            c[j][0] *= ATT_SCALE; c[j][1] *= ATT_SCALE;
            c[j][2] *= ATT_SCALE; c[j][3] *= ATT_SCALE;
            if (diag) {
                if (key     > r0) c[j][0] = -1e30f;
                if (key + 1 > r0) c[j][1] = -1e30f;
                if (key     > r1) c[j][2] = -1e30f;
                if (key + 1 > r1) c[j][3] = -1e30f;
            }
        }

        // ---- online softmax ----
        float mx0 = m0, mx1 = m1;
        #pragma unroll
        for (int j = 0; j < 8; j++) {
            mx0 = fmaxf(mx0, fmaxf(c[j][0], c[j][1]));
            mx1 = fmaxf(mx1, fmaxf(c[j][2], c[j][3]));
        }
        mx0 = fmaxf(mx0, __shfl_xor_sync(0xffffffffu, mx0, 1));
        mx0 = fmaxf(mx0, __shfl_xor_sync(0xffffffffu, mx0, 2));
        mx1 = fmaxf(mx1, __shfl_xor_sync(0xffffffffu, mx1, 1));
        mx1 = fmaxf(mx1, __shfl_xor_sync(0xffffffffu, mx1, 2));
        const float corr0 = __expf(m0 - mx0);
        const float corr1 = __expf(m1 - mx1);
        m0 = mx0; m1 = mx1;
        l0 *= corr0; l1 *= corr1;
        #pragma unroll
        for (int n = 0; n < 16; n++) {
            o[n][0] *= corr0; o[n][1] *= corr0;
            o[n][2] *= corr1; o[n][3] *= corr1;
        }

        // ---- P = exp(S - m);  O += P V ----
        float s0 = 0.f, s1 = 0.f;
        const int srcA = (lane & ~3) | (tg >> 1);
        const int srcB = srcA + 2;
        const bool odd = tg & 1;
        #pragma unroll
        for (int kb = 0; kb < 8; kb++) {
            const float e00 = __expf(c[kb][0] - m0);
            const float e01 = __expf(c[kb][1] - m0);
            const float e10 = __expf(c[kb][2] - m1);
            const float e11 = __expf(c[kb][3] - m1);
            s0 += e00 + e01; s1 += e10 + e11;

            // rearrange P (C-layout) -> A-fragment layout (warp-local)
            const float f00 = __shfl_sync(0xffffffffu, e00, srcA);
            const float f01 = __shfl_sync(0xffffffffu, e01, srcA);
            const float f02 = __shfl_sync(0xffffffffu, e00, srcB);
            const float f03 = __shfl_sync(0xffffffffu, e01, srcB);
            const float f10 = __shfl_sync(0xffffffffu, e10, srcA);
            const float f11 = __shfl_sync(0xffffffffu, e11, srcA);
            const float f12 = __shfl_sync(0xffffffffu, e10, srcB);
            const float f13 = __shfl_sync(0xffffffffu, e11, srcB);
            u32 af[4];
            af[0] = f2tf32(odd ? f01 : f00);
            af[1] = f2tf32(odd ? f11 : f10);
            af[2] = f2tf32(odd ? f03 : f02);
            af[3] = f2tf32(odd ? f13 : f12);

            #pragma unroll
            for (int n = 0; n < 16; n++) {
                u32 bf[2];
                const u32* bb = sV + (kb * 8 + tg) * SV_LD + n * 8 + g;
                bf[0] = bb[0];
                bf[1] = bb[4 * SV_LD];
                mma_tf32(o[n], af, bf);
            }
        }
        s0 += __shfl_xor_sync(0xffffffffu, s0, 1);
        s0 += __shfl_xor_sync(0xffffffffu, s0, 2);
        s1 += __shfl_xor_sync(0xffffffffu, s1, 1);
        s1 += __shfl_xor_sync(0xffffffffu, s1, 2);
        l0 += s0; l1 += s1;
    }

    // ---- epilogue ----
    const float inv0 = 1.f / l0;
    const float inv1 = 1.f / l1;
    float* cp0 = g_C + (size_t)r0 * HIDDEN + h * HD;
    float* cp1 = g_C + (size_t)r1 * HIDDEN + h * HD;
    #pragma unroll
    for (int n = 0; n < 16; n++) {
        const int col = n * 8 + 2 * tg;
        *(float2*)(cp0 + col) = make_float2(o[n][0] * inv0, o[n][1] * inv0);
        *(float2*)(cp1 + col) = make_float2(o[n][2] * inv1, o[n][3] * inv1);
    }
}

// ---------------------------------------------------------------------------
extern "C" void kernel_launch(void* const* d_in, const int* in_sizes, int n_in,
                              void* d_out, int out_size)
{
    const float* hs   = (const float*)d_in[0];
    const float* cosT = (const float*)d_in[1];
    const float* sinT = (const float*)d_in[2];
    // d_in[3] = attention_mask (pure causal; applied analytically)
    const float* Wq = (const float*)d_in[4];
    const float* bq = (const float*)d_in[5];
    const float* Wk = (const float*)d_in[6];
    const float* bk = (const float*)d_in[7];
    const float* Wv = (const float*)d_in[8];
    const float* bv = (const float*)d_in[9];
    const float* Wo = (const float*)d_in[10];
    float* out = (float*)d_out;

    cudaFuncSetAttribute(attn_mma_kernel,
                         cudaFuncAttributeMaxDynamicSharedMemorySize, ATTN_SMEM);

    mma_gemm_kernel<<<dim3(16, 16), 256>>>(hs, Wq, bq, nullptr, HIDDEN, HIDDEN, 0, 1);
    mma_gemm_kernel<<<dim3(2,  16), 256>>>(hs, Wk, bk, nullptr, HIDDEN, KVW,    0, 2);
    mma_gemm_kernel<<<dim3(2,  16), 256>>>(hs, Wv, bv, nullptr, HIDDEN, KVW,    0, 3);

    rope_kernel<<<(SEQ * NH  * 64 + 255) / 256, 256>>>(cosT, sinT, NH, 1);
    rope_kernel<<<(SEQ * NKV * 64 + 255) / 256, 256>>>(cosT, sinT, NKV, 0);

    attn_mma_kernel<<<dim3(16, 16), 256, ATTN_SMEM>>>();

    mma_gemm_kernel<<<dim3(16, 16), 256>>>(nullptr, Wo, nullptr, out, HIDDEN, HIDDEN, 1, 0);
}

// round 8
// speedup vs baseline: 4.5587x; 1.2693x over previous
#include <cuda_runtime.h>

typedef unsigned int u32;

#define SEQ 2048
#define HIDDEN 2048
#define NH 16
#define NKV 2
#define HD 128
#define KVW (NKV*HD)          // 256
#define ATT_SCALE 0.08838834764831845f

// ---------------- scratch (no allocations allowed) ----------------
__device__ float g_Q[SEQ*HIDDEN];
__device__ float g_K[SEQ*KVW];
__device__ float g_V[SEQ*KVW];
__device__ float g_C[SEQ*HIDDEN];

// ---------------- helpers ----------------
__device__ __forceinline__ u32 f2tf32(float f) {
    u32 r;
    asm("cvt.rna.tf32.f32 %0, %1;" : "=r"(r) : "f"(f));
    return r;
}
__device__ __forceinline__ void mma_tf32(float* c, const u32* a, const u32* b) {
    asm volatile(
        "mma.sync.aligned.m16n8k8.row.col.f32.tf32.tf32.f32 "
        "{%0,%1,%2,%3}, {%4,%5,%6,%7}, {%8,%9}, {%0,%1,%2,%3};"
        : "+f"(c[0]), "+f"(c[1]), "+f"(c[2]), "+f"(c[3])
        : "r"(a[0]), "r"(a[1]), "r"(a[2]), "r"(a[3]),
          "r"(b[0]), "r"(b[1]));
}

// ---------------------------------------------------------------------------
// tf32 mma.sync GEMM: C[M,N] = A[M,K] @ W[K,N] (+bias)
// 128x128 block tile, 8 warps (2M x 4N -> 64x32 each), K-chunk 32.
// Double-buffered smem, ONE barrier per chunk; staging stores overlap compute.
// Fragment math / staging layout / epilogue identical to the proven kernel.
// mode 1: fused QKV (blockIdx.x selects W/bias/dst), mode 0: O-proj to outF.
// ---------------------------------------------------------------------------
#define G_SA_LD 36
#define G_SB_LD 132
#define G_STAGE_A (128*G_SA_LD)              // 4608 words
#define G_STAGE (G_STAGE_A + 32*G_SB_LD)     // 8832 words
#define G_SMEM (2*G_STAGE*4)                 // 70656 B

__device__ __forceinline__ void gemm_stage_store(
    u32* buf, const float4* ar, const float4* br,
    int arow, int ak4, int bkrow, int bcol4)
{
    #pragma unroll
    for (int p = 0; p < 4; p++) {
        u32* da = buf + (arow + p * 32) * G_SA_LD + ak4;
        da[0] = f2tf32(ar[p].x); da[1] = f2tf32(ar[p].y);
        da[2] = f2tf32(ar[p].z); da[3] = f2tf32(ar[p].w);
        u32* db = buf + G_STAGE_A + (bkrow + p * 8) * G_SB_LD + bcol4;
        db[0] = f2tf32(br[p].x); db[1] = f2tf32(br[p].y);
        db[2] = f2tf32(br[p].z); db[3] = f2tf32(br[p].w);
    }
}

__global__ void __launch_bounds__(256) mma_gemm_kernel(
    const float* __restrict__ A_ext,
    const float* __restrict__ W0, const float* __restrict__ W1,
    const float* __restrict__ W2,
    const float* __restrict__ b0, const float* __restrict__ b1,
    const float* __restrict__ b2,
    float* __restrict__ outF, int mode)
{
    extern __shared__ u32 smg[];
    const int t = threadIdx.x;
    const int wid = t >> 5, lane = t & 31;
    const int warpM = wid & 1, warpN = wid >> 1;
    const int g = lane >> 2, tg = lane & 3;
    const int row0 = blockIdx.y * 128;

    // per-block operand / destination select
    const float* A; const float* W; const float* bias; float* C; int Nw; int col0;
    if (mode == 1) {
        A = A_ext;
        const int bn = blockIdx.x;
        if (bn < 16)      { W = W0; bias = b0; C = g_Q; Nw = HIDDEN; col0 = bn * 128; }
        else if (bn < 18) { W = W1; bias = b1; C = g_K; Nw = KVW;    col0 = (bn - 16) * 128; }
        else              { W = W2; bias = b2; C = g_V; Nw = KVW;    col0 = (bn - 18) * 128; }
    } else {
        A = g_C; W = W0; bias = nullptr; C = outF; Nw = HIDDEN; col0 = blockIdx.x * 128;
    }

    float c[4][4][4];
    #pragma unroll
    for (int i = 0; i < 4; i++)
        #pragma unroll
        for (int j = 0; j < 4; j++)
            #pragma unroll
            for (int r = 0; r < 4; r++) c[i][j][r] = 0.f;

    const int arow = t >> 3;           // 0..31 (4 passes of 32 rows)
    const int ak4  = (t & 7) * 4;      // k offset 0..28
    const int bkrow = t >> 5;          // 0..7 (4 passes of 8 k-rows)
    const int bcol4 = (t & 31) * 4;    // 0..124

    const float* Ap = A + (size_t)(row0 + arow) * HIDDEN + ak4;
    const float* Bp = W + (size_t)bkrow * Nw + col0 + bcol4;
    const size_t aRow32 = (size_t)32 * HIDDEN;
    const size_t bRow8  = (size_t)8 * Nw;
    const int NCH = HIDDEN >> 5;       // 64

    float4 ar[4], br[4];
    // chunk 0 -> regs -> buf0
    #pragma unroll
    for (int p = 0; p < 4; p++) {
        ar[p] = *(const float4*)(Ap + p * aRow32);
        br[p] = *(const float4*)(Bp + p * bRow8);
    }
    gemm_stage_store(smg, ar, br, arow, ak4, bkrow, bcol4);
    // chunk 1 -> regs
    #pragma unroll
    for (int p = 0; p < 4; p++) {
        ar[p] = *(const float4*)(Ap + 32 + p * aRow32);
        br[p] = *(const float4*)(Bp + (size_t)32 * Nw + p * bRow8);
    }

    const int bcolw = warpN * 32;

    for (int ch = 0; ch < NCH; ch++) {
        __syncthreads();   // all warps done with iter ch-1; buf[ch&1] stores visible

        // store chunk ch+1 into the non-active buffer (overlaps with compute below)
        if (ch + 1 < NCH)
            gemm_stage_store(smg + ((ch + 1) & 1) * G_STAGE, ar, br,
                             arow, ak4, bkrow, bcol4);

        // issue global loads for chunk ch+2 (latency hidden by compute)
        if (ch + 2 < NCH) {
            const int ko = (ch + 2) * 32;
            #pragma unroll
            for (int p = 0; p < 4; p++) {
                ar[p] = *(const float4*)(Ap + ko + p * aRow32);
                br[p] = *(const float4*)(Bp + (size_t)ko * Nw + p * bRow8);
            }
        }

        // compute chunk ch from buf[ch&1]
        const u32* sA = smg + (ch & 1) * G_STAGE;
        const u32* sB = sA + G_STAGE_A;
        const u32* sAw = sA + (warpM * 64) * G_SA_LD;

        #pragma unroll
        for (int ks = 0; ks < 4; ks++) {
            const int kb = ks * 8;
            u32 af[4][4], bf[4][2];
            #pragma unroll
            for (int i = 0; i < 4; i++) {
                const u32* base = sAw + (i * 16 + g) * G_SA_LD + kb + tg;
                af[i][0] = base[0];
                af[i][1] = base[8 * G_SA_LD];
                af[i][2] = base[4];
                af[i][3] = base[8 * G_SA_LD + 4];
            }
            #pragma unroll
            for (int j = 0; j < 4; j++) {
                const u32* base = sB + (kb + tg) * G_SB_LD + bcolw + j * 8 + g;
                bf[j][0] = base[0];
                bf[j][1] = base[4 * G_SB_LD];
            }
            #pragma unroll
            for (int i = 0; i < 4; i++)
                #pragma unroll
                for (int j = 0; j < 4; j++)
                    mma_tf32(c[i][j], af[i], bf[j]);
        }
    }

    // epilogue (proven)
    #pragma unroll
    for (int i = 0; i < 4; i++) {
        const int r0e = row0 + warpM * 64 + i * 16 + g;
        #pragma unroll
        for (int j = 0; j < 4; j++) {
            const int col = col0 + warpN * 32 + j * 8 + 2 * tg;
            float bb0 = 0.f, bb1 = 0.f;
            if (bias) { bb0 = bias[col]; bb1 = bias[col + 1]; }
            *(float2*)(C + (size_t)r0e * Nw + col) =
                make_float2(c[i][j][0] + bb0, c[i][j][1] + bb1);
            *(float2*)(C + (size_t)(r0e + 8) * Nw + col) =
                make_float2(c[i][j][2] + bb0, c[i][j][3] + bb1);
        }
    }
}

// ---------------------------------------------------------------------------
// RoPE in place (round-4 verbatim)
// ---------------------------------------------------------------------------
__global__ void rope_kernel(const float* __restrict__ cosT,
                            const float* __restrict__ sinT,
                            int nheads, int which)
{
    float* X = which ? g_Q : g_K;
    const int idx = blockIdx.x * blockDim.x + threadIdx.x;
    const int total = SEQ * nheads * 64;
    if (idx >= total) return;
    const int d = idx & 63;
    const int h = (idx >> 6) % nheads;
    const int s = idx / (64 * nheads);

    const float c1 = cosT[s * HD + d];
    const float s1 = sinT[s * HD + d];
    const float c2 = cosT[s * HD + d + 64];
    const float s2 = sinT[s * HD + d + 64];

    float* p = X + (size_t)s * (nheads * HD) + h * HD + d;
    const float x1 = p[0];
    const float x2 = p[64];
    p[0]  = x1 * c1 - x2 * s1;
    p[64] = x2 * c2 + x1 * s2;
}

// ---------------------------------------------------------------------------
// mma.sync tf32 flash attention (round-4 verbatim)
// ---------------------------------------------------------------------------
#define SK_LD 132
#define SV_LD 136
#define SK_WORDS (64 * SK_LD)
#define SV_WORDS (64 * SV_LD)
#define ATTN_SMEM ((SK_WORDS + SV_WORDS) * 4)

__global__ void __launch_bounds__(256, 1) attn_mma_kernel()
{
    extern __shared__ u32 smem[];
    u32* sK = smem;                 // [64][SK_LD]
    u32* sV = smem + SK_WORDS;      // [64][SV_LD]

    const int t = threadIdx.x;
    const int lane = t & 31, wid = t >> 5;
    const int g = lane >> 2, tg = lane & 3;
    const int qt = 15 - blockIdx.x;          // heavy tiles first
    const int h  = blockIdx.y;
    const int kvh = h >> 3;
    const int qbase = qt * 128 + wid * 16;
    const int r0 = qbase + g, r1 = qbase + g + 8;

    // Q fragments (tf32) in registers: rows r0/r1, all 128 dims
    u32 qf[16][4];
    const float* Qp = g_Q + (size_t)qbase * HIDDEN + h * HD;
    #pragma unroll
    for (int ks = 0; ks < 16; ks++) {
        qf[ks][0] = f2tf32(Qp[(size_t)g * HIDDEN + ks * 8 + tg]);
        qf[ks][1] = f2tf32(Qp[(size_t)(g + 8) * HIDDEN + ks * 8 + tg]);
        qf[ks][2] = f2tf32(Qp[(size_t)g * HIDDEN + ks * 8 + tg + 4]);
        qf[ks][3] = f2tf32(Qp[(size_t)(g + 8) * HIDDEN + ks * 8 + tg + 4]);
    }

    float o[16][4];
    #pragma unroll
    for (int n = 0; n < 16; n++)
        #pragma unroll
        for (int r = 0; r < 4; r++) o[n][r] = 0.f;
    float m0 = -1e30f, m1 = -1e30f, l0 = 0.f, l1 = 0.f;

    const int ntiles = 2 * qt + 2;

    for (int kt = 0; kt < ntiles; kt++) {
        __syncthreads();
        // stage K/V tile (64x128) as tf32
        #pragma unroll
        for (int p = 0; p < 8; p++) {
            const int idx = p * 256 + t;
            const int r = idx >> 5;
            const int c4 = (idx & 31) << 2;
            const size_t goff = (size_t)(kt * 64 + r) * KVW + kvh * HD + c4;
            float4 kk = *(const float4*)&g_K[goff];
            float4 vv = *(const float4*)&g_V[goff];
            u32* dk = sK + r * SK_LD + c4;
            dk[0] = f2tf32(kk.x); dk[1] = f2tf32(kk.y);
            dk[2] = f2tf32(kk.z); dk[3] = f2tf32(kk.w);
            u32* dv = sV + r * SV_LD + c4;
            dv[0] = f2tf32(vv.x); dv[1] = f2tf32(vv.y);
            dv[2] = f2tf32(vv.z); dv[3] = f2tf32(vv.w);
        }
        __syncthreads();

        if (kt * 64 > qbase + 15) continue;   // fully masked for this warp

        // ---- S = Q K^T (16 x 64) ----
        float c[8][4];
        #pragma unroll
        for (int j = 0; j < 8; j++)
            #pragma unroll
            for (int r = 0; r < 4; r++) c[j][r] = 0.f;

        #pragma unroll
        for (int ks = 0; ks < 16; ks++) {
            #pragma unroll
            for (int j = 0; j < 8; j++) {
                u32 bf[2];
                const u32* bb = sK + (j * 8 + g) * SK_LD + ks * 8 + tg;
                bf[0] = bb[0];
                bf[1] = bb[4];
                mma_tf32(c[j], qf[ks], bf);
            }
        }

        // ---- scale + causal mask ----
        const bool diag = (kt * 64 + 63 > qbase);
        #pragma unroll
        for (int j = 0; j < 8; j++) {
            const int key = kt * 64 + j * 8 + 2 * tg;
            c[j][0] *= ATT_SCALE; c[j][1] *= ATT_SCALE;
            c[j][2] *= ATT_SCALE; c[j][3] *= ATT_SCALE;
            if (diag) {
                if (key     > r0) c[j][0] = -1e30f;
                if (key + 1 > r0) c[j][1] = -1e30f;
                if (key     > r1) c[j][2] = -1e30f;
                if (key + 1 > r1) c[j][3] = -1e30f;
            }
        }

        // ---- online softmax ----
        float mx0 = m0, mx1 = m1;
        #pragma unroll
        for (int j = 0; j < 8; j++) {
            mx0 = fmaxf(mx0, fmaxf(c[j][0], c[j][1]));
            mx1 = fmaxf(mx1, fmaxf(c[j][2], c[j][3]));
        }
        mx0 = fmaxf(mx0, __shfl_xor_sync(0xffffffffu, mx0, 1));
        mx0 = fmaxf(mx0, __shfl_xor_sync(0xffffffffu, mx0, 2));
        mx1 = fmaxf(mx1, __shfl_xor_sync(0xffffffffu, mx1, 1));
        mx1 = fmaxf(mx1, __shfl_xor_sync(0xffffffffu, mx1, 2));
        const float corr0 = __expf(m0 - mx0);
        const float corr1 = __expf(m1 - mx1);
        m0 = mx0; m1 = mx1;
        l0 *= corr0; l1 *= corr1;
        #pragma unroll
        for (int n = 0; n < 16; n++) {
            o[n][0] *= corr0; o[n][1] *= corr0;
            o[n][2] *= corr1; o[n][3] *= corr1;
        }

        // ---- P = exp(S - m);  O += P V ----
        float s0 = 0.f, s1 = 0.f;
        const int srcA = (lane & ~3) | (tg >> 1);
        const int srcB = srcA + 2;
        const bool odd = tg & 1;
        #pragma unroll
        for (int kb = 0; kb < 8; kb++) {
            const float e00 = __expf(c[kb][0] - m0);
            const float e01 = __expf(c[kb][1] - m0);
            const float e10 = __expf(c[kb][2] - m1);
            const float e11 = __expf(c[kb][3] - m1);
            s0 += e00 + e01; s1 += e10 + e11;

            const float f00 = __shfl_sync(0xffffffffu, e00, srcA);
            const float f01 = __shfl_sync(0xffffffffu, e01, srcA);
            const float f02 = __shfl_sync(0xffffffffu, e00, srcB);
            const float f03 = __shfl_sync(0xffffffffu, e01, srcB);
            const float f10 = __shfl_sync(0xffffffffu, e10, srcA);
            const float f11 = __shfl_sync(0xffffffffu, e11, srcA);
            const float f12 = __shfl_sync(0xffffffffu, e10, srcB);
            const float f13 = __shfl_sync(0xffffffffu, e11, srcB);
            u32 af[4];
            af[0] = f2tf32(odd ? f01 : f00);
            af[1] = f2tf32(odd ? f11 : f10);
            af[2] = f2tf32(odd ? f03 : f02);
            af[3] = f2tf32(odd ? f13 : f12);

            #pragma unroll
            for (int n = 0; n < 16; n++) {
                u32 bf[2];
                const u32* bb = sV + (kb * 8 + tg) * SV_LD + n * 8 + g;
                bf[0] = bb[0];
                bf[1] = bb[4 * SV_LD];
                mma_tf32(o[n], af, bf);
            }
        }
        s0 += __shfl_xor_sync(0xffffffffu, s0, 1);
        s0 += __shfl_xor_sync(0xffffffffu, s0, 2);
        s1 += __shfl_xor_sync(0xffffffffu, s1, 1);
        s1 += __shfl_xor_sync(0xffffffffu, s1, 2);
        l0 += s0; l1 += s1;
    }

    // ---- epilogue ----
    const float inv0 = 1.f / l0;
    const float inv1 = 1.f / l1;
    float* cp0 = g_C + (size_t)r0 * HIDDEN + h * HD;
    float* cp1 = g_C + (size_t)r1 * HIDDEN + h * HD;
    #pragma unroll
    for (int n = 0; n < 16; n++) {
        const int col = n * 8 + 2 * tg;
        *(float2*)(cp0 + col) = make_float2(o[n][0] * inv0, o[n][1] * inv0);
        *(float2*)(cp1 + col) = make_float2(o[n][2] * inv1, o[n][3] * inv1);
    }
}

// ---------------------------------------------------------------------------
extern "C" void kernel_launch(void* const* d_in, const int* in_sizes, int n_in,
                              void* d_out, int out_size)
{
    const float* hs   = (const float*)d_in[0];
    const float* cosT = (const float*)d_in[1];
    const float* sinT = (const float*)d_in[2];
    // d_in[3] = attention_mask (pure causal; applied analytically)
    const float* Wq = (const float*)d_in[4];
    const float* bq = (const float*)d_in[5];
    const float* Wk = (const float*)d_in[6];
    const float* bk = (const float*)d_in[7];
    const float* Wv = (const float*)d_in[8];
    const float* bv = (const float*)d_in[9];
    const float* Wo = (const float*)d_in[10];
    float* out = (float*)d_out;

    cudaFuncSetAttribute(mma_gemm_kernel,
                         cudaFuncAttributeMaxDynamicSharedMemorySize, G_SMEM);
    cudaFuncSetAttribute(attn_mma_kernel,
                         cudaFuncAttributeMaxDynamicSharedMemorySize, ATTN_SMEM);

    // fused QKV projection: blocks 0-15 -> Q, 16-17 -> K, 18-19 -> V
    mma_gemm_kernel<<<dim3(20, 16), 256, G_SMEM>>>(
        hs, Wq, Wk, Wv, bq, bk, bv, nullptr, 1);

    rope_kernel<<<(SEQ * NH  * 64 + 255) / 256, 256>>>(cosT, sinT, NH, 1);
    rope_kernel<<<(SEQ * NKV * 64 + 255) / 256, 256>>>(cosT, sinT, NKV, 0);

    attn_mma_kernel<<<dim3(16, 16), 256, ATTN_SMEM>>>();

    // O projection
    mma_gemm_kernel<<<dim3(16, 16), 256, G_SMEM>>>(
        g_C, Wo, nullptr, nullptr, nullptr, nullptr, nullptr, out, 0);
}